// round 14
// baseline (speedup 1.0000x reference)
#include <cuda_runtime.h>
#include <math.h>

// Problem constants
#define NN    512
#define CS    384
#define CZ    128
#define HH    12
#define CH    16
#define PQN   4
#define PVN   8
#define DPROJ 1152
#define FH    (CH + PVN*3 + PVN + CZ)  // 176
#define FEAT  (HH*FH)                  // 2112
#define COUT  384
#define DK    28                       // combined qk+point dim

// segment bases inside g_proj row
#define OFF_PQ_Q   0
#define OFF_PQ_K   192
#define OFF_PQ_V   384
#define OFF_PQ_QP  576
#define OFF_PQ_KP  720
#define OFF_PQ_VP  864

// ---------------- scratch ----------------
__device__ __align__(16) float g_proj[NN*DPROJ];
__device__ __align__(16) float g_qk  [HH*NN*DK];            // Q' = [0.25*q, qpg]
__device__ __align__(16) float g_kk  [HH*NN*DK];            // K' = [k, kpg]
__device__ __align__(16) float g_sqk [HH*NN];               // 0.5*|kpg|^2
__device__ __align__(16) float g_vpg [NN*HH*PVN*3];
__device__ __align__(16) float g_feat[NN*FEAT];
__device__ __align__(16) float g_zb  [(size_t)HH*NN*NN];    // [h][n][m]
__device__ __align__(16) float g_att [(size_t)HH*NN*NN];    // logits -> weights
__device__ __align__(16) float g_vout[NN*HH*40];            // v+vpg weighted sums
#define SPLITS 6
__device__ __align__(16) float g_opart[SPLITS][NN][COUT];

// =================== fused projection SGEMM ===========================
#define PT_M 64
#define PT_N 48
#define PT_K 16
__global__ void proj_gemm_kernel(const float* __restrict__ s,
    const float* __restrict__ wq,  const float* __restrict__ bq,
    const float* __restrict__ wk,  const float* __restrict__ bk,
    const float* __restrict__ wv,  const float* __restrict__ bv,
    const float* __restrict__ wqp, const float* __restrict__ bqp,
    const float* __restrict__ wkp, const float* __restrict__ bkp,
    const float* __restrict__ wvp, const float* __restrict__ bvp) {
    int bt = blockIdx.y;
    const float *W, *B; int Dout, base, t;
    if      (bt < 4)  { W=wq;  B=bq;  Dout=192; base=OFF_PQ_Q;  t=bt; }
    else if (bt < 8)  { W=wk;  B=bk;  Dout=192; base=OFF_PQ_K;  t=bt-4; }
    else if (bt < 12) { W=wv;  B=bv;  Dout=192; base=OFF_PQ_V;  t=bt-8; }
    else if (bt < 15) { W=wqp; B=bqp; Dout=144; base=OFF_PQ_QP; t=bt-12; }
    else if (bt < 18) { W=wkp; B=bkp; Dout=144; base=OFF_PQ_KP; t=bt-15; }
    else              { W=wvp; B=bvp; Dout=288; base=OFF_PQ_VP; t=bt-18; }
    int col0 = t*PT_N;
    int n0   = blockIdx.x*PT_M;

    __shared__ float sA[PT_K][PT_M];
    __shared__ float sB[PT_K][PT_N];
    int tid = threadIdx.x;           // 192
    int tx = tid % 12, ty = tid / 12;
    float4 acc[4] = {};

    for (int k0 = 0; k0 < CS; k0 += PT_K) {
        for (int i = tid; i < PT_M*PT_K/4; i += 192) {
            int m = i >> 2, k4 = (i & 3) * 4;
            float4 v = *(const float4*)(s + (size_t)(n0+m)*CS + k0 + k4);
            sA[k4+0][m]=v.x; sA[k4+1][m]=v.y; sA[k4+2][m]=v.z; sA[k4+3][m]=v.w;
        }
        for (int i = tid; i < PT_K*PT_N/4; i += 192) {
            int k = i / 12, c4 = (i % 12) * 4;
            *(float4*)&sB[k][c4] = *(const float4*)(W + (size_t)(k0+k)*Dout + col0 + c4);
        }
        __syncthreads();
        #pragma unroll
        for (int kk = 0; kk < PT_K; kk++) {
            float4 b = *(float4*)&sB[kk][tx*4];
            float4 a = *(float4*)&sA[kk][ty*4];
            acc[0].x += a.x*b.x; acc[0].y += a.x*b.y; acc[0].z += a.x*b.z; acc[0].w += a.x*b.w;
            acc[1].x += a.y*b.x; acc[1].y += a.y*b.y; acc[1].z += a.y*b.z; acc[1].w += a.y*b.w;
            acc[2].x += a.z*b.x; acc[2].y += a.z*b.y; acc[2].z += a.z*b.z; acc[2].w += a.z*b.w;
            acc[3].x += a.w*b.x; acc[3].y += a.w*b.y; acc[3].z += a.w*b.z; acc[3].w += a.w*b.w;
        }
        __syncthreads();
    }
    float4 bias4 = *(const float4*)(B + col0 + tx*4);
    #pragma unroll
    for (int r = 0; r < 4; r++) {
        float4 o = acc[r];
        o.x += bias4.x; o.y += bias4.y; o.z += bias4.z; o.w += bias4.w;
        *(float4*)(g_proj + (size_t)(n0+ty*4+r)*DPROJ + base + col0 + tx*4) = o;
    }
}

// =================== prep: rotate points, build Q'/K'/sqk/vpg =========
__global__ void prep_kernel(const float* __restrict__ rot,
                            const float* __restrict__ trans) {
    int n = blockIdx.x, t = threadIdx.x;   // 192 threads
    __shared__ float R[9], T[3];
    __shared__ float kpg_s[144];
    if (t < 9) R[t] = rot[n*9 + t];
    if (t < 3) T[t] = trans[n*3 + t];
    __syncthreads();

    {
        int h = t / 16, c = t % 16;
        g_qk[(size_t)h*NN*DK + n*DK + c] = g_proj[(size_t)n*DPROJ + t] * 0.25f;
        g_kk[(size_t)h*NN*DK + n*DK + c] = g_proj[(size_t)n*DPROJ + 192 + t];
    }
    if (t < 48) {               // qp
        const float* l = g_proj + (size_t)n*DPROJ + OFF_PQ_QP + t*3;
        float l0=l[0], l1=l[1], l2=l[2];
        int h = t/4, p = t%4;
        float* dst = g_qk + (size_t)h*NN*DK + n*DK + 16 + p*3;
        dst[0] = R[0]*l0 + R[1]*l1 + R[2]*l2 + T[0];
        dst[1] = R[3]*l0 + R[4]*l1 + R[5]*l2 + T[1];
        dst[2] = R[6]*l0 + R[7]*l1 + R[8]*l2 + T[2];
    } else if (t < 96) {        // kp
        int tt = t - 48;
        const float* l = g_proj + (size_t)n*DPROJ + OFF_PQ_KP + tt*3;
        float l0=l[0], l1=l[1], l2=l[2];
        int h = tt/4, p = tt%4;
        float g0 = R[0]*l0 + R[1]*l1 + R[2]*l2 + T[0];
        float g1 = R[3]*l0 + R[4]*l1 + R[5]*l2 + T[1];
        float g2 = R[6]*l0 + R[7]*l1 + R[8]*l2 + T[2];
        float* dst = g_kk + (size_t)h*NN*DK + n*DK + 16 + p*3;
        dst[0]=g0; dst[1]=g1; dst[2]=g2;
        kpg_s[tt*3+0]=g0; kpg_s[tt*3+1]=g1; kpg_s[tt*3+2]=g2;
    } else {                    // vp
        int tt = t - 96;
        const float* l = g_proj + (size_t)n*DPROJ + OFF_PQ_VP + tt*3;
        float l0=l[0], l1=l[1], l2=l[2];
        float* dst = g_vpg + (size_t)n*288 + tt*3;
        dst[0] = R[0]*l0 + R[1]*l1 + R[2]*l2 + T[0];
        dst[1] = R[3]*l0 + R[4]*l1 + R[5]*l2 + T[1];
        dst[2] = R[6]*l0 + R[7]*l1 + R[8]*l2 + T[2];
    }
    __syncthreads();
    if (t < HH) {
        float s = 0.f;
        #pragma unroll
        for (int j = 0; j < 12; j++) { float v = kpg_s[t*12 + j]; s += v*v; }
        g_sqk[t*NN + n] = 0.5f * s;
    }
}

// =================== zb GEMM: smem-staged, one block per n ============
#define ZKC 16
__global__ void zb_gemm_kernel(const float* __restrict__ z,
                               const float* __restrict__ wb) {
    __shared__ float z_s[NN*(ZKC+1)];
    __shared__ float wb_s[CZ*HH];
    int n = blockIdx.x, tid = threadIdx.x;   // 128
    for (int i = tid; i < CZ*HH; i += 128) wb_s[i] = wb[i];

    float acc[4][HH] = {};
    const float* zrow = z + (size_t)n*NN*CZ;

    for (int c = 0; c < CZ/ZKC; c++) {
        __syncthreads();
        for (int i = tid; i < NN*ZKC/4; i += 128) {
            int row = i >> 2, c4 = (i & 3) * 4;
            float4 v = *(const float4*)(zrow + (size_t)row*CZ + c*ZKC + c4);
            float* d = z_s + row*(ZKC+1) + c4;
            d[0]=v.x; d[1]=v.y; d[2]=v.z; d[3]=v.w;
        }
        __syncthreads();
        #pragma unroll
        for (int k = 0; k < ZKC; k++) {
            const float* wrow = wb_s + (c*ZKC + k)*HH;
            float zv[4];
            #pragma unroll
            for (int r = 0; r < 4; r++) zv[r] = z_s[(tid + 128*r)*(ZKC+1) + k];
            #pragma unroll
            for (int h = 0; h < HH; h++) {
                float w = wrow[h];
                acc[0][h] += zv[0]*w;
                acc[1][h] += zv[1]*w;
                acc[2][h] += zv[2]*w;
                acc[3][h] += zv[3]*w;
            }
        }
    }
    #pragma unroll
    for (int h = 0; h < HH; h++) {
        float* dst = g_zb + (size_t)h*NN*NN + (size_t)n*NN;
        #pragma unroll
        for (int r = 0; r < 4; r++) dst[tid + 128*r] = acc[r][h];
    }
}

// =================== logits GEMM: per-head 64x64x28 + epilogue ========
__global__ void logits_gemm_kernel(const int* __restrict__ mask) {
    int m0 = blockIdx.x*64, n0 = blockIdx.y*64, h = blockIdx.z;
    __shared__ float Qs[DK][64];
    __shared__ float Ks[DK][64];
    int tid = threadIdx.x;   // 256
    int tx = tid & 15, ty = tid >> 4;

    const float4* qsrc = (const float4*)(g_qk + (size_t)h*NN*DK + (size_t)n0*DK);
    const float4* ksrc = (const float4*)(g_kk + (size_t)h*NN*DK + (size_t)m0*DK);
    for (int i = tid; i < 64*7; i += 256) {
        int row = i / 7, q = i % 7;
        float4 v = qsrc[row*7 + q];
        Qs[q*4+0][row]=v.x; Qs[q*4+1][row]=v.y; Qs[q*4+2][row]=v.z; Qs[q*4+3][row]=v.w;
        float4 w = ksrc[row*7 + q];
        Ks[q*4+0][row]=w.x; Ks[q*4+1][row]=w.y; Ks[q*4+2][row]=w.z; Ks[q*4+3][row]=w.w;
    }
    __syncthreads();

    float4 acc[4] = {};
    #pragma unroll
    for (int k = 0; k < DK; k++) {
        float4 b = *(float4*)&Ks[k][tx*4];
        float4 a = *(float4*)&Qs[k][ty*4];
        acc[0].x += a.x*b.x; acc[0].y += a.x*b.y; acc[0].z += a.x*b.z; acc[0].w += a.x*b.w;
        acc[1].x += a.y*b.x; acc[1].y += a.y*b.y; acc[1].z += a.y*b.z; acc[1].w += a.y*b.w;
        acc[2].x += a.z*b.x; acc[2].y += a.z*b.y; acc[2].z += a.z*b.z; acc[2].w += a.z*b.w;
        acc[3].x += a.w*b.x; acc[3].y += a.w*b.y; acc[3].z += a.w*b.z; acc[3].w += a.w*b.w;
    }

    float4 sq = *(const float4*)(g_sqk + h*NN + m0 + tx*4);
    int4 mm = *(const int4*)(mask + m0 + tx*4);
    #pragma unroll
    for (int r = 0; r < 4; r++) {
        int row = n0 + ty*4 + r;
        int mn = __ldg(mask + row);
        float4 zbv = *(const float4*)(g_zb + (size_t)h*NN*NN + (size_t)row*NN + m0 + tx*4);
        float4 o;
        o.x = acc[r].x + zbv.x - sq.x;
        o.y = acc[r].y + zbv.y - sq.y;
        o.z = acc[r].z + zbv.z - sq.z;
        o.w = acc[r].w + zbv.w - sq.w;
        if (mn == 0) { o.x=o.y=o.z=o.w=-1e30f; }
        else {
            if (mm.x == 0) o.x = -1e30f;
            if (mm.y == 0) o.y = -1e30f;
            if (mm.z == 0) o.z = -1e30f;
            if (mm.w == 0) o.w = -1e30f;
        }
        *(float4*)(g_att + (size_t)h*NN*NN + (size_t)row*NN + m0 + tx*4) = o;
    }
}

// =================== softmax: one block per n, warp per head ==========
__global__ void softmax_kernel() {
    int n = blockIdx.x;
    int w = threadIdx.x >> 5, lane = threadIdx.x & 31;   // 384 threads
    float* row = g_att + ((size_t)w*NN + (size_t)n)*NN;
    float4* row4 = (float4*)row;

    float4 v[4];
    #pragma unroll
    for (int i = 0; i < 4; i++) v[i] = row4[lane + 32*i];

    float mx = -1e30f;
    #pragma unroll
    for (int i = 0; i < 4; i++)
        mx = fmaxf(mx, fmaxf(fmaxf(v[i].x, v[i].y), fmaxf(v[i].z, v[i].w)));
    #pragma unroll
    for (int o = 16; o; o >>= 1) mx = fmaxf(mx, __shfl_xor_sync(0xffffffffu, mx, o));

    float s = 0.f;
    #pragma unroll
    for (int i = 0; i < 4; i++) {
        v[i].x = __expf(v[i].x - mx); v[i].y = __expf(v[i].y - mx);
        v[i].z = __expf(v[i].z - mx); v[i].w = __expf(v[i].w - mx);
        s += v[i].x + v[i].y + v[i].z + v[i].w;
    }
    #pragma unroll
    for (int o = 16; o; o >>= 1) s += __shfl_xor_sync(0xffffffffu, s, o);
    float inv = 1.f / s;
    #pragma unroll
    for (int i = 0; i < 4; i++) {
        v[i].x *= inv; v[i].y *= inv; v[i].z *= inv; v[i].w *= inv;
        row4[lane + 32*i] = v[i];
    }
}

// =================== vsum GEMM: OUT_h[64n x 40] = W_h @ [V|VP]_h ======
#define VS_MC 32
__global__ void vsum_kernel() {
    int n0 = blockIdx.x*64, h = blockIdx.y;
    __shared__ float Ws[64][VS_MC+1];
    __shared__ float Vs[VS_MC][41];
    int tid = threadIdx.x;   // 128
    int rg = tid >> 3, tc = tid & 7;
    float acc[4][5] = {};

    for (int m0 = 0; m0 < NN; m0 += VS_MC) {
        #pragma unroll
        for (int jj = 0; jj < 4; jj++) {
            int idx = tid + 128*jj;            // 512 float4
            int row = idx >> 3, q = idx & 7;
            float4 v = *(const float4*)(g_att + ((size_t)h*NN + (n0+row))*NN + m0 + q*4);
            float* d = &Ws[row][q*4];
            d[0]=v.x; d[1]=v.y; d[2]=v.z; d[3]=v.w;
        }
        for (int i = tid; i < VS_MC*40; i += 128) {
            int m = i / 40, c = i % 40;
            float val;
            if (c < 16) val = g_proj[(size_t)(m0+m)*DPROJ + OFF_PQ_V + h*CH + c];
            else        val = g_vpg[(size_t)(m0+m)*288 + h*24 + (c-16)];
            Vs[m][c] = val;
        }
        __syncthreads();
        #pragma unroll 8
        for (int mk = 0; mk < VS_MC; mk++) {
            float wv[4], vv[5];
            #pragma unroll
            for (int r = 0; r < 4; r++) wv[r] = Ws[rg*4+r][mk];
            #pragma unroll
            for (int j = 0; j < 5; j++) vv[j] = Vs[mk][tc*5+j];
            #pragma unroll
            for (int r = 0; r < 4; r++)
                #pragma unroll
                for (int j = 0; j < 5; j++) acc[r][j] += wv[r]*vv[j];
        }
        __syncthreads();
    }
    #pragma unroll
    for (int r = 0; r < 4; r++)
        #pragma unroll
        for (int j = 0; j < 5; j++)
            g_vout[(size_t)(n0+rg*4+r)*HH*40 + h*40 + tc*5+j] = acc[r][j];
}

// =================== wsum: pair features + finalize ===================
__global__ void attn_wsum_kernel(const float* __restrict__ z,
                                 const float* __restrict__ trans,
                                 const float* __restrict__ rot) {
    __shared__ __align__(16) float w_s[NN*HH];     // [m][h], 24 KB
    __shared__ float acc_s[HH*132];
    __shared__ float R[9], T[3];

    int n = blockIdx.x, tid = threadIdx.x;   // 256
    #pragma unroll
    for (int h = 0; h < HH; h++) {
        const float* src = g_att + ((size_t)h*NN + (size_t)n)*NN;
        for (int i = tid; i < NN; i += 256) w_s[i*HH + h] = src[i];
    }
    for (int i = tid; i < HH*132; i += 256) acc_s[i] = 0.f;
    if (tid < 9) R[tid] = rot[n*9 + tid];
    if (tid < 3) T[tid] = trans[n*3 + tid];
    __syncthreads();

    {
        int c_g    = tid & 31;
        int stripe = tid >> 5;
        float4 acc[HH];
        #pragma unroll
        for (int h = 0; h < HH; h++) acc[h] = make_float4(0.f,0.f,0.f,0.f);

        const float4* zrow = (const float4*)(z + (size_t)n*NN*CZ);
        int mbeg = stripe*64;
        #pragma unroll 4
        for (int it = 0; it < 64; it++) {
            int m = mbeg + it;
            float4 zv = __ldg(zrow + m*32 + c_g);
            const float4* wr = (const float4*)(w_s + m*HH);
            float4 w0 = wr[0], w1 = wr[1], w2 = wr[2];
            const float* wf = (const float*)&w0;
            #pragma unroll
            for (int h = 0; h < 4; h++) {
                float wv = wf[h];
                acc[h].x += wv*zv.x; acc[h].y += wv*zv.y;
                acc[h].z += wv*zv.z; acc[h].w += wv*zv.w;
            }
            const float* wf1 = (const float*)&w1;
            #pragma unroll
            for (int h = 0; h < 4; h++) {
                float wv = wf1[h];
                acc[4+h].x += wv*zv.x; acc[4+h].y += wv*zv.y;
                acc[4+h].z += wv*zv.z; acc[4+h].w += wv*zv.w;
            }
            const float* wf2 = (const float*)&w2;
            #pragma unroll
            for (int h = 0; h < 4; h++) {
                float wv = wf2[h];
                acc[8+h].x += wv*zv.x; acc[8+h].y += wv*zv.y;
                acc[8+h].z += wv*zv.z; acc[8+h].w += wv*zv.w;
            }
        }
        #pragma unroll
        for (int h = 0; h < HH; h++) {
            float* dst = acc_s + h*132 + c_g*4;
            atomicAdd(dst+0, acc[h].x);
            atomicAdd(dst+1, acc[h].y);
            atomicAdd(dst+2, acc[h].z);
            atomicAdd(dst+3, acc[h].w);
        }
    }
    __syncthreads();

    // pair features
    for (int i = tid; i < HH*CZ; i += 256) {
        int h = i >> 7, c = i & 127;
        g_feat[(size_t)n*FEAT + h*FH + 48 + c] = acc_s[h*132 + c];
    }
    // scalar v
    if (tid < HH*CH) {
        int h = tid >> 4, j = tid & 15;
        g_feat[(size_t)n*FEAT + h*FH + j] = g_vout[(size_t)n*HH*40 + h*40 + j];
    }
    // points (FIX: was tid>=224 with only 32 active threads; needs 96)
    if (tid < HH*PVN) {
        int h = tid / PVN, p = tid % PVN;
        const float* vo = g_vout + (size_t)n*HH*40 + h*40 + 16 + p*3;
        float x0_ = vo[0] - T[0];
        float x1_ = vo[1] - T[1];
        float x2_ = vo[2] - T[2];
        float l0 = R[0]*x0_ + R[3]*x1_ + R[6]*x2_;
        float l1 = R[1]*x0_ + R[4]*x1_ + R[7]*x2_;
        float l2 = R[2]*x0_ + R[5]*x1_ + R[8]*x2_;
        g_feat[(size_t)n*FEAT + h*FH + 16 + p*3 + 0] = l0;
        g_feat[(size_t)n*FEAT + h*FH + 16 + p*3 + 1] = l1;
        g_feat[(size_t)n*FEAT + h*FH + 16 + p*3 + 2] = l2;
        g_feat[(size_t)n*FEAT + h*FH + 40 + p] = sqrtf(l0*l0 + l1*l1 + l2*l2);
    }
}

// =================== output projection: split-K, 8x4 micro ============
#define OT_M 128
#define OT_N 64
#define OT_K 16
#define KSPLIT (FEAT/SPLITS)   // 352
__global__ void out_gemm_kernel(const float* __restrict__ wo) {
    int n0   = blockIdx.x*OT_M;
    int col0 = blockIdx.y*OT_N;
    int sp   = blockIdx.z;
    __shared__ float sA[OT_K][OT_M];
    __shared__ float sB[OT_K][OT_N];
    int tid = threadIdx.x;   // 256
    int tx = tid & 15, ty = tid >> 4;
    float4 acc[8] = {};
    int kbeg = sp*KSPLIT, kend = kbeg + KSPLIT;
    for (int k0 = kbeg; k0 < kend; k0 += OT_K) {
        for (int i = tid; i < OT_M*OT_K/4; i += 256) {
            int m = i >> 2, k4 = (i & 3) * 4;
            float4 v = *(const float4*)(g_feat + (size_t)(n0+m)*FEAT + k0 + k4);
            sA[k4+0][m]=v.x; sA[k4+1][m]=v.y; sA[k4+2][m]=v.z; sA[k4+3][m]=v.w;
        }
        {
            int k = tid >> 4, c4 = (tid & 15) * 4;
            *(float4*)&sB[k][c4] = *(const float4*)(wo + (size_t)(k0+k)*COUT + col0 + c4);
        }
        __syncthreads();
        #pragma unroll
        for (int kk = 0; kk < OT_K; kk++) {
            float4 b  = *(float4*)&sB[kk][tx*4];
            float4 a0 = *(float4*)&sA[kk][ty*8];
            float4 a1 = *(float4*)&sA[kk][ty*8+4];
            const float* af0 = (const float*)&a0;
            const float* af1 = (const float*)&a1;
            #pragma unroll
            for (int r = 0; r < 4; r++) {
                float av = af0[r];
                acc[r].x += av*b.x; acc[r].y += av*b.y; acc[r].z += av*b.z; acc[r].w += av*b.w;
            }
            #pragma unroll
            for (int r = 0; r < 4; r++) {
                float av = af1[r];
                acc[4+r].x += av*b.x; acc[4+r].y += av*b.y; acc[4+r].z += av*b.z; acc[4+r].w += av*b.w;
            }
        }
        __syncthreads();
    }
    #pragma unroll
    for (int r = 0; r < 8; r++)
        *(float4*)&g_opart[sp][n0+ty*8+r][col0+tx*4] = acc[r];
}

__global__ void out_reduce_kernel(const float* __restrict__ bo,
                                  float* __restrict__ out) {
    int n = blockIdx.x, o = threadIdx.x;
    float a = bo[o];
    #pragma unroll
    for (int sp = 0; sp < SPLITS; sp++) a += g_opart[sp][n][o];
    out[(size_t)n*COUT + o] = a;
}

// ---------------- launch ---------------------------------------------------
extern "C" void kernel_launch(void* const* d_in, const int* in_sizes, int n_in,
                              void* d_out, int out_size) {
    const float* s     = (const float*)d_in[0];
    const float* z     = (const float*)d_in[1];
    const float* trans = (const float*)d_in[2];
    const float* rot   = (const float*)d_in[3];
    const int*   mask  = (const int*)  d_in[4];
    const float* wq    = (const float*)d_in[5];
    const float* bq    = (const float*)d_in[6];
    const float* wk    = (const float*)d_in[7];
    const float* bk    = (const float*)d_in[8];
    const float* wv    = (const float*)d_in[9];
    const float* bv    = (const float*)d_in[10];
    const float* wqp   = (const float*)d_in[11];
    const float* bqp   = (const float*)d_in[12];
    const float* wkp   = (const float*)d_in[13];
    const float* bkp   = (const float*)d_in[14];
    const float* wvp   = (const float*)d_in[15];
    const float* bvp   = (const float*)d_in[16];
    const float* wb    = (const float*)d_in[17];
    const float* bb    = (const float*)d_in[18];
    const float* wo    = (const float*)d_in[19];
    const float* bo    = (const float*)d_in[20];
    float* out = (float*)d_out;
    (void)bb;  // bb cancels in softmax

    zb_gemm_kernel<<<NN, 128>>>(z, wb);
    proj_gemm_kernel<<<dim3(NN/PT_M, 24), 192>>>(s,
        wq, bq, wk, bk, wv, bv, wqp, bqp, wkp, bkp, wvp, bvp);
    prep_kernel<<<NN, 192>>>(rot, trans);
    logits_gemm_kernel<<<dim3(8, 8, HH), 256>>>(mask);
    softmax_kernel<<<NN, 384>>>();
    vsum_kernel<<<dim3(8, HH), 128>>>();
    attn_wsum_kernel<<<NN, 256>>>(z, trans, rot);
    out_gemm_kernel<<<dim3(NN/OT_M, COUT/OT_N, SPLITS), 256>>>(wo);
    out_reduce_kernel<<<NN, COUT>>>(bo, out);
}